// round 14
// baseline (speedup 1.0000x reference)
#include <cuda_runtime.h>

// out = clip(x + laplace * mask, 0, 1), elementwise, 38,535,168 fp32.
// HBM-roofline streaming kernel: 3 reads + 1 write, 616.6 MB irreducible.
// R12: persistent grid-stride launch (148 SMs x 8 CTAs resident, zero wave
// transitions). Prior sweep (kernel us): VPT1 84.3 | VPT2-pred 83.0 |
// VPT2-unguarded 83.2 | VPT4 83.7 | 256-bit 84.2 | 512t 84.1 — all ~7 TB/s.

#define THREADS 256
#define PERSISTENT_BLOCKS (148 * 8)   // 8 CTAs/SM resident on 148 SMs

__global__ void __launch_bounds__(THREADS)
rrn_clip_persistent(const float4* __restrict__ x,
                    const float4* __restrict__ lap,
                    const float4* __restrict__ mask,
                    float4* __restrict__ out,
                    int n4) {
    const int stride = gridDim.x * THREADS;
    for (int i = blockIdx.x * THREADS + threadIdx.x; i < n4; i += stride) {
        float4 xv = __ldcs(x + i);
        float4 lv = __ldcs(lap + i);
        float4 mv = __ldcs(mask + i);
        float4 r;
        r.x = __saturatef(fmaf(lv.x, mv.x, xv.x));
        r.y = __saturatef(fmaf(lv.y, mv.y, xv.y));
        r.z = __saturatef(fmaf(lv.z, mv.z, xv.z));
        r.w = __saturatef(fmaf(lv.w, mv.w, xv.w));
        __stcs(out + i, r);
    }
}

// Generic scalar remainder (covers n % 4 != 0; not launched for this shape).
__global__ void rrn_clip_rem(const float* __restrict__ x,
                             const float* __restrict__ lap,
                             const float* __restrict__ mask,
                             float* __restrict__ out,
                             int start, int n) {
    int i = start + blockIdx.x * blockDim.x + threadIdx.x;
    if (i >= n) return;
    out[i] = __saturatef(fmaf(__ldcs(lap + i), __ldcs(mask + i), __ldcs(x + i)));
}

extern "C" void kernel_launch(void* const* d_in, const int* in_sizes, int n_in,
                              void* d_out, int out_size) {
    // metadata order: x, eps (dead scalar), laplace_noise, mask
    const float* x    = (const float*)d_in[0];
    const float* lap  = (const float*)d_in[2];
    const float* mask = (const float*)d_in[3];
    float* out        = (float*)d_out;

    int n  = in_sizes[0];
    int n4 = n >> 2;

    if (n4 > 0) {
        rrn_clip_persistent<<<PERSISTENT_BLOCKS, THREADS>>>(
            (const float4*)x, (const float4*)lap, (const float4*)mask,
            (float4*)out, n4);
    }
    int tail_start = n4 << 2;
    if (n - tail_start > 0) {
        rrn_clip_rem<<<1, 32>>>(x, lap, mask, out, tail_start, n);
    }
}

// round 15
// speedup vs baseline: 1.0301x; 1.0301x over previous
#include <cuda_runtime.h>

// out = clip(x + laplace * mask, 0, 1), elementwise, 38,535,168 fp32.
// HBM-roofline streaming kernel: 3 reads + 1 write, 616.6 MB irreducible.
//
// FINAL (R14 = revert to R3's measured-best): VPT=2 float4 per thread,
// 256 threads/block, streaming (.cs) loads/stores, front-batched LDGs.
// Full structural sweep (kernel us @ ~7.0 TB/s):
//   VPT1 84.3 | VPT2-pred 83.0 (best) | VPT2-unguarded 83.2 | VPT4 83.7
//   256-bit 84.2 | 512t 84.1 | persistent 88.3 (regression: resident CTAs
//   starve the DRAM scheduler's address diversity).
// Conclusion: pinned at the HBM roofline (~88% of 8 TB/s spec for a 3:1
// R:W mix); all compute pipes <5% busy. Remaining gap is bus turnaround.

#define VPT 2  // float4s per thread
#define THREADS 256

__global__ void rrn_clip_kernel(const float4* __restrict__ x,
                                const float4* __restrict__ lap,
                                const float4* __restrict__ mask,
                                float4* __restrict__ out,
                                int n4) {
    int base = (blockIdx.x * THREADS) * VPT + threadIdx.x;

    float4 xv[VPT], lv[VPT], mv[VPT];
    // Front-batch all loads (streaming, evict-first)
    #pragma unroll
    for (int j = 0; j < VPT; j++) {
        int i = base + j * THREADS;
        if (i < n4) {
            xv[j] = __ldcs(x + i);
            lv[j] = __ldcs(lap + i);
            mv[j] = __ldcs(mask + i);
        }
    }
    #pragma unroll
    for (int j = 0; j < VPT; j++) {
        int i = base + j * THREADS;
        if (i < n4) {
            float4 r;
            r.x = __saturatef(fmaf(lv[j].x, mv[j].x, xv[j].x));
            r.y = __saturatef(fmaf(lv[j].y, mv[j].y, xv[j].y));
            r.z = __saturatef(fmaf(lv[j].z, mv[j].z, xv[j].z));
            r.w = __saturatef(fmaf(lv[j].w, mv[j].w, xv[j].w));
            __stcs(out + i, r);
        }
    }
}

// Scalar tail for n not divisible by 4 (not hit for this shape).
__global__ void rrn_clip_tail(const float* __restrict__ x,
                              const float* __restrict__ lap,
                              const float* __restrict__ mask,
                              float* __restrict__ out,
                              int start, int n) {
    int i = start + blockIdx.x * blockDim.x + threadIdx.x;
    if (i >= n) return;
    out[i] = __saturatef(fmaf(__ldcs(lap + i), __ldcs(mask + i), __ldcs(x + i)));
}

extern "C" void kernel_launch(void* const* d_in, const int* in_sizes, int n_in,
                              void* d_out, int out_size) {
    // metadata order: x, eps (dead scalar), laplace_noise, mask
    const float* x    = (const float*)d_in[0];
    const float* lap  = (const float*)d_in[2];
    const float* mask = (const float*)d_in[3];
    float* out        = (float*)d_out;

    int n  = in_sizes[0];
    int n4 = n >> 2;

    if (n4 > 0) {
        int blocks = (n4 + THREADS * VPT - 1) / (THREADS * VPT);
        rrn_clip_kernel<<<blocks, THREADS>>>(
            (const float4*)x, (const float4*)lap, (const float4*)mask,
            (float4*)out, n4);
    }
    int tail_start = n4 << 2;
    if (n - tail_start > 0) {
        rrn_clip_tail<<<1, 32>>>(x, lap, mask, out, tail_start, n);
    }
}